// round 9
// baseline (speedup 1.0000x reference)
#include <cuda_runtime.h>
#include <cstdint>
#include <math.h>

#define BB 8
#define NN 1024
#define HH 12
#define DHD 64
#define DIM 768
#define DH  768
#define E3  2304
#define NTOK (BB*NN)
#define KTOT 768
#define NBH (BB*HH)   // 96

// Scratch (device globals; no runtime allocation allowed)
__device__ float g_qkv[(size_t)NTOK * E3];
__device__ float g_o[(size_t)NTOK * DH];
__device__ float g_vt[(size_t)NBH * DHD * NN];   // [bh][dim][key]

__device__ __forceinline__ uint32_t hi_bits(float x) {
    return __float_as_uint(x) & 0xFFFFE000u;
}
__device__ __forceinline__ uint32_t fau(float x) { return __float_as_uint(x); }

__device__ __forceinline__ void mma_tf32(float* d, const uint32_t* a,
                                         const uint32_t* b) {
    asm volatile(
        "mma.sync.aligned.m16n8k8.row.col.f32.tf32.tf32.f32 "
        "{%0,%1,%2,%3}, {%4,%5,%6,%7}, {%8,%9}, {%0,%1,%2,%3};"
        : "+f"(d[0]), "+f"(d[1]), "+f"(d[2]), "+f"(d[3])
        : "r"(a[0]), "r"(a[1]), "r"(a[2]), "r"(a[3]), "r"(b[0]), "r"(b[1]));
}

__device__ __forceinline__ uint32_t smem_u32(const void* p) {
    uint32_t a;
    asm("{ .reg .u64 t; cvta.to.shared.u64 t, %1; cvt.u32.u64 %0, t; }"
        : "=r"(a) : "l"(p));
    return a;
}
__device__ __forceinline__ void cp_async16(uint32_t dst, const void* src) {
    asm volatile("cp.async.cg.shared.global [%0], [%1], 16;"
                 :: "r"(dst), "l"(src));
}
#define CP_COMMIT() asm volatile("cp.async.commit_group;" ::: "memory")
#define CP_WAIT1()  asm volatile("cp.async.wait_group 1;" ::: "memory")

// ===========================================================================
// Split-tf32 GEMM, 3-stage cp.async pipeline: one __syncthreads per chunk.
// Raw A/B in smem; hi/lo split in registers. 128x128 tile, 8 warps, K=32.
// ===========================================================================
#define SROW 36                          // 144 B row stride (16B-aligned)
#define SMAT (128 * SROW)                // floats per matrix per stage
#define NST 3
#define SMEM_MM (NST * 2 * SMAT * 4)     // 108 KB

__global__ __launch_bounds__(256, 2) void mm_hmma(const float* __restrict__ A,
                                                  const float* __restrict__ Bm,
                                                  const float* __restrict__ bias,
                                                  float* __restrict__ C, int ldc) {
    extern __shared__ float smem[];
    const uint32_t sb = smem_u32(smem);

    const int tid = threadIdx.x;
    const int wid = tid >> 5, lane = tid & 31;
    const int gid = lane >> 2, tig = lane & 3;
    const int wm = wid & 1;
    const int wn = wid >> 1;
    const int m0 = blockIdx.y * 128;
    const int n0 = blockIdx.x * 128;

    // staging coords: 2 threads/row; each covers 4 x 16B slots per matrix
    const int srow = tid >> 1;                 // 0..127
    const int scol = (tid & 1) * 4;            // slot base 0 or 4

    float acc[4][4][4] = {};

    // Prologue: stage chunks 0 and 1 into stages 0 and 1
    #pragma unroll
    for (int st = 0; st < 2; st++) {
        const int k0 = st * 32;
        const uint32_t bufA = sb + (2 * st) * SMAT * 4;
        const uint32_t bufB = sb + (2 * st + 1) * SMAT * 4;
        #pragma unroll
        for (int p = 0; p < 4; p++) {
            const int c4 = scol + p;           // float4 slot 0..7
            cp_async16(bufA + (srow * SROW + c4 * 4) * 4,
                       A + (size_t)(m0 + srow) * KTOT + k0 + c4 * 4);
            cp_async16(bufB + (srow * SROW + c4 * 4) * 4,
                       Bm + (size_t)(n0 + srow) * KTOT + k0 + c4 * 4);
        }
        CP_COMMIT();
    }

    const int NCH = KTOT / 32;                 // 24
    for (int ch = 0; ch < NCH; ch++) {
        CP_WAIT1();          // chunk ch landed (chunk ch+1 may be in flight)
        __syncthreads();     // all warps done with chunk ch-1; data visible

        // Prefetch chunk ch+2 into stage (ch+2)%3 (freed by chunk ch-1)
        if (ch + 2 < NCH) {
            const int k0 = (ch + 2) * 32;
            const int st = (ch + 2) % NST;
            const uint32_t bufA = sb + (2 * st) * SMAT * 4;
            const uint32_t bufB = sb + (2 * st + 1) * SMAT * 4;
            #pragma unroll
            for (int p = 0; p < 4; p++) {
                const int c4 = scol + p;
                cp_async16(bufA + (srow * SROW + c4 * 4) * 4,
                           A + (size_t)(m0 + srow) * KTOT + k0 + c4 * 4);
                cp_async16(bufB + (srow * SROW + c4 * 4) * 4,
                           Bm + (size_t)(n0 + srow) * KTOT + k0 + c4 * 4);
            }
        }
        CP_COMMIT();         // commit every iter (possibly empty): keeps counts

        const int st = ch % NST;
        const float* sA = smem + (2 * st) * SMAT;
        const float* sB = smem + (2 * st + 1) * SMAT;

        #pragma unroll
        for (int kk = 0; kk < 32; kk += 8) {
            uint32_t bh[4][2], bl[4][2];
            #pragma unroll
            for (int u = 0; u < 4; u++) {
                const int rb = (wn * 32 + u * 8 + gid) * SROW + kk + tig;
                float b0 = sB[rb], b1 = sB[rb + 4];
                bh[u][0] = hi_bits(b0);
                bh[u][1] = hi_bits(b1);
                bl[u][0] = fau(b0 - __uint_as_float(bh[u][0]));
                bl[u][1] = fau(b1 - __uint_as_float(bh[u][1]));
            }
            #pragma unroll
            for (int t = 0; t < 4; t++) {
                const int rb = (wm * 64 + t * 16 + gid) * SROW + kk + tig;
                float a0 = sA[rb];
                float a1 = sA[rb + 8 * SROW];
                float a2 = sA[rb + 4];
                float a3 = sA[rb + 8 * SROW + 4];
                uint32_t ah[4] = {hi_bits(a0), hi_bits(a1),
                                  hi_bits(a2), hi_bits(a3)};
                uint32_t al[4] = {fau(a0 - __uint_as_float(ah[0])),
                                  fau(a1 - __uint_as_float(ah[1])),
                                  fau(a2 - __uint_as_float(ah[2])),
                                  fau(a3 - __uint_as_float(ah[3]))};
                #pragma unroll
                for (int u = 0; u < 4; u++) {
                    mma_tf32(acc[t][u], ah, bh[u]);
                    mma_tf32(acc[t][u], ah, bl[u]);
                    mma_tf32(acc[t][u], al, bh[u]);
                }
            }
        }
    }

    const int rbase = m0 + wm * 64;
    const int cbase = n0 + wn * 32;
    #pragma unroll
    for (int t = 0; t < 4; t++) {
        #pragma unroll
        for (int u = 0; u < 4; u++) {
            const int c = cbase + u * 8 + tig * 2;
            float b0 = 0.f, b1 = 0.f;
            if (bias) { b0 = bias[c]; b1 = bias[c + 1]; }
            const int r0 = rbase + t * 16 + gid;
            *(float2*)(C + (size_t)r0 * ldc + c) =
                make_float2(acc[t][u][0] + b0, acc[t][u][1] + b1);
            *(float2*)(C + (size_t)(r0 + 8) * ldc + c) =
                make_float2(acc[t][u][2] + b0, acc[t][u][3] + b1);
        }
    }
}

// ===========================================================================
// Pre-pass: V -> V^T [bh][dim][key].
// ===========================================================================
__global__ __launch_bounds__(256) void prep_v() {
    __shared__ float sv[64][68];
    const int bh = blockIdx.y;
    const int kt = blockIdx.x;
    const int b = bh / HH, h = bh - b * HH;
    const int tid = threadIdx.x;
    #pragma unroll
    for (int p = 0; p < 4; p++) {
        const int j = tid + p * 256;
        const int key = j >> 4, c4 = (j & 15) * 4;
        float4 v = *(const float4*)(g_qkv +
            ((size_t)(b * NN + kt * 64 + key)) * E3 + h * 192 + 128 + c4);
        *(float4*)&sv[key][c4] = v;
    }
    __syncthreads();
    #pragma unroll
    for (int p = 0; p < 4; p++) {
        const int j = tid + p * 256;
        const int d = j >> 4, key4 = (j & 15) * 4;
        float4 o = make_float4(sv[key4 + 0][d], sv[key4 + 1][d],
                               sv[key4 + 2][d], sv[key4 + 3][d]);
        *(float4*)(g_vt + ((size_t)bh * 64 + d) * NN + kt * 64 + key4) = o;
    }
}

// ===========================================================================
// Flash attention, split-tf32 HMMA (unchanged — proven).
// ===========================================================================
#define ASTR 68
#define ATILE (64 * ASTR)
#define ATTN_SMEM (3 * ATILE * 4)   // 52224 B

__global__ __launch_bounds__(128, 4) void attn_hmma() {
    extern __shared__ float sm[];
    float* sQ = sm;
    float* sK = sQ + ATILE;
    float* sV = sK + ATILE;

    const int bh = blockIdx.y;
    const int q0 = blockIdx.x * 64;
    const int tid = threadIdx.x;
    const int wid = tid >> 5, lane = tid & 31;
    const int gid = lane >> 2, tig = lane & 3;
    const int b = bh / HH, h = bh - b * HH;
    const int r0 = wid * 16 + gid;
    const int qb = lane & ~3;
    const int src0 = qb + (tig >> 1);
    const int src1 = src0 + 2;
    const int esel = tig & 1;

    {
        const float* qg = g_qkv + ((size_t)(b * NN + q0)) * E3 + h * 192;
        #pragma unroll
        for (int p = 0; p < 8; p++) {
            const int j = tid + p * 128;
            const int r = j >> 4, c4 = (j & 15) * 4;
            float4 v = *(const float4*)(qg + (size_t)r * E3 + c4);
            *(float4*)&sQ[r * ASTR + c4] =
                make_float4(v.x * 8.f, v.y * 8.f, v.z * 8.f, v.w * 8.f);
        }
    }

    float oa[8][4] = {};
    float mrow0 = -1e30f, mrow1 = -1e30f, lrow0 = 0.f, lrow1 = 0.f;

    for (int kt = 0; kt < 16; kt++) {
        __syncthreads();
        {
            const float* kg = g_qkv + ((size_t)(b * NN + kt * 64)) * E3 + h * 192 + 64;
            const float* vg = g_vt + ((size_t)bh * 64) * NN + kt * 64;
            #pragma unroll
            for (int p = 0; p < 8; p++) {
                const int j = tid + p * 128;
                const int r = j >> 4, c4 = (j & 15) * 4;
                *(float4*)&sK[r * ASTR + c4] = *(const float4*)(kg + (size_t)r * E3 + c4);
                *(float4*)&sV[r * ASTR + c4] = *(const float4*)(vg + (size_t)r * NN + c4);
            }
        }
        __syncthreads();

        float s[8][4] = {};
        #pragma unroll
        for (int kk = 0; kk < 64; kk += 8) {
            float a0 = sQ[r0 * ASTR + kk + tig];
            float a1 = sQ[(r0 + 8) * ASTR + kk + tig];
            float a2 = sQ[r0 * ASTR + kk + tig + 4];
            float a3 = sQ[(r0 + 8) * ASTR + kk + tig + 4];
            uint32_t ah[4] = {hi_bits(a0), hi_bits(a1), hi_bits(a2), hi_bits(a3)};
            uint32_t al[4] = {fau(a0 - __uint_as_float(ah[0])),
                              fau(a1 - __uint_as_float(ah[1])),
                              fau(a2 - __uint_as_float(ah[2])),
                              fau(a3 - __uint_as_float(ah[3]))};
            #pragma unroll
            for (int u = 0; u < 8; u++) {
                const int n = u * 8 + gid;
                float b0 = sK[n * ASTR + kk + tig];
                float b1 = sK[n * ASTR + kk + tig + 4];
                uint32_t bh[2] = {hi_bits(b0), hi_bits(b1)};
                uint32_t bl[2] = {fau(b0 - __uint_as_float(bh[0])),
                                  fau(b1 - __uint_as_float(bh[1]))};
                mma_tf32(s[u], ah, bh);
                mma_tf32(s[u], ah, bl);
                mma_tf32(s[u], al, bh);
            }
        }

        float mt0 = -1e30f, mt1 = -1e30f;
        #pragma unroll
        for (int u = 0; u < 8; u++) {
            mt0 = fmaxf(mt0, fmaxf(s[u][0], s[u][1]));
            mt1 = fmaxf(mt1, fmaxf(s[u][2], s[u][3]));
        }
        #pragma unroll
        for (int off = 1; off < 4; off <<= 1) {
            mt0 = fmaxf(mt0, __shfl_xor_sync(0xffffffffu, mt0, off));
            mt1 = fmaxf(mt1, __shfl_xor_sync(0xffffffffu, mt1, off));
        }
        const float mn0 = fmaxf(mrow0, mt0);
        const float mn1 = fmaxf(mrow1, mt1);
        const float f0 = __expf(mrow0 - mn0);
        const float f1 = __expf(mrow1 - mn1);
        float ls0 = 0.f, ls1 = 0.f;
        #pragma unroll
        for (int u = 0; u < 8; u++) {
            s[u][0] = __expf(s[u][0] - mn0);
            s[u][1] = __expf(s[u][1] - mn0);
            s[u][2] = __expf(s[u][2] - mn1);
            s[u][3] = __expf(s[u][3] - mn1);
            ls0 += s[u][0] + s[u][1];
            ls1 += s[u][2] + s[u][3];
        }
        #pragma unroll
        for (int off = 1; off < 4; off <<= 1) {
            ls0 += __shfl_xor_sync(0xffffffffu, ls0, off);
            ls1 += __shfl_xor_sync(0xffffffffu, ls1, off);
        }
        lrow0 = lrow0 * f0 + ls0;  mrow0 = mn0;
        lrow1 = lrow1 * f1 + ls1;  mrow1 = mn1;

        #pragma unroll
        for (int u = 0; u < 8; u++) {
            oa[u][0] *= f0; oa[u][1] *= f0;
            oa[u][2] *= f1; oa[u][3] *= f1;
        }

        #pragma unroll
        for (int kk = 0; kk < 8; kk++) {
            float v00 = __shfl_sync(0xffffffffu, s[kk][0], src0);
            float v01 = __shfl_sync(0xffffffffu, s[kk][1], src0);
            float v10 = __shfl_sync(0xffffffffu, s[kk][2], src0);
            float v11 = __shfl_sync(0xffffffffu, s[kk][3], src0);
            float w00 = __shfl_sync(0xffffffffu, s[kk][0], src1);
            float w01 = __shfl_sync(0xffffffffu, s[kk][1], src1);
            float w10 = __shfl_sync(0xffffffffu, s[kk][2], src1);
            float w11 = __shfl_sync(0xffffffffu, s[kk][3], src1);
            float a0 = esel ? v01 : v00;
            float a1 = esel ? v11 : v10;
            float a2 = esel ? w01 : w00;
            float a3 = esel ? w11 : w10;
            uint32_t ah[4] = {hi_bits(a0), hi_bits(a1), hi_bits(a2), hi_bits(a3)};
            uint32_t al[4] = {fau(a0 - __uint_as_float(ah[0])),
                              fau(a1 - __uint_as_float(ah[1])),
                              fau(a2 - __uint_as_float(ah[2])),
                              fau(a3 - __uint_as_float(ah[3]))};
            #pragma unroll
            for (int u = 0; u < 8; u++) {
                const int n = u * 8 + gid;
                float b0 = sV[n * ASTR + kk * 8 + tig];
                float b1 = sV[n * ASTR + kk * 8 + tig + 4];
                uint32_t bh[2] = {hi_bits(b0), hi_bits(b1)};
                uint32_t bl[2] = {fau(b0 - __uint_as_float(bh[0])),
                                  fau(b1 - __uint_as_float(bh[1]))};
                mma_tf32(oa[u], ah, bh);
                mma_tf32(oa[u], ah, bl);
                mma_tf32(oa[u], al, bh);
            }
        }
    }

    const float il0 = 1.f / lrow0;
    const float il1 = 1.f / lrow1;
    #pragma unroll
    for (int u = 0; u < 8; u++) {
        const int col = h * 64 + u * 8 + 2 * tig;
        *(float2*)&g_o[((size_t)(b * NN + q0 + r0)) * DH + col] =
            make_float2(oa[u][0] * il0, oa[u][1] * il0);
        *(float2*)&g_o[((size_t)(b * NN + q0 + r0 + 8)) * DH + col] =
            make_float2(oa[u][2] * il1, oa[u][3] * il1);
    }
}

// ===========================================================================
extern "C" void kernel_launch(void* const* d_in, const int* in_sizes, int n_in,
                              void* d_out, int out_size) {
    const float* img  = (const float*)d_in[0];   // [8,1024,768]
    const float* Wqkv = (const float*)d_in[1];   // [2304,768]
    const float* Wfc  = (const float*)d_in[2];   // [768,768]
    const float* bfc  = (const float*)d_in[3];   // [768]
    float* out = (float*)d_out;                  // [8,1024,768]

    void* qkvp = nullptr;
    void* op = nullptr;
    cudaGetSymbolAddress(&qkvp, g_qkv);
    cudaGetSymbolAddress(&op, g_o);

    cudaFuncSetAttribute(mm_hmma, cudaFuncAttributeMaxDynamicSharedMemorySize,
                         SMEM_MM);
    cudaFuncSetAttribute(attn_hmma, cudaFuncAttributeMaxDynamicSharedMemorySize,
                         ATTN_SMEM);

    // 1) QKV projection
    mm_hmma<<<dim3(E3 / 128, NTOK / 128), 256, SMEM_MM>>>(img, Wqkv, nullptr,
                                                          (float*)qkvp, E3);
    // 2) V transpose
    prep_v<<<dim3(16, NBH), 256>>>();
    // 3) Flash attention
    attn_hmma<<<dim3(NN / 64, NBH), 128, ATTN_SMEM>>>();
    // 4) Output projection + bias
    mm_hmma<<<dim3(DIM / 128, NTOK / 128), 256, SMEM_MM>>>((const float*)op, Wfc,
                                                           bfc, out, DIM);
}

// round 11
// speedup vs baseline: 1.0591x; 1.0591x over previous
#include <cuda_runtime.h>
#include <cstdint>
#include <math.h>

#define BB 8
#define NN 1024
#define HH 12
#define DHD 64
#define DIM 768
#define DH  768
#define E3  2304
#define NTOK (BB*NN)
#define KTOT 768
#define NBH (BB*HH)   // 96

// Scratch (device globals; no runtime allocation allowed)
__device__ float g_qkv[(size_t)NTOK * E3];
__device__ float g_o[(size_t)NTOK * DH];
__device__ float g_vt[(size_t)NBH * DHD * NN];   // [bh][dim][key]

__device__ __forceinline__ uint32_t hi_bits(float x) {
    return __float_as_uint(x) & 0xFFFFE000u;
}
__device__ __forceinline__ uint32_t fau(float x) { return __float_as_uint(x); }

__device__ __forceinline__ void mma_tf32(float* d, const uint32_t* a,
                                         const uint32_t* b) {
    asm volatile(
        "mma.sync.aligned.m16n8k8.row.col.f32.tf32.tf32.f32 "
        "{%0,%1,%2,%3}, {%4,%5,%6,%7}, {%8,%9}, {%0,%1,%2,%3};"
        : "+f"(d[0]), "+f"(d[1]), "+f"(d[2]), "+f"(d[3])
        : "r"(a[0]), "r"(a[1]), "r"(a[2]), "r"(a[3]), "r"(b[0]), "r"(b[1]));
}

__device__ __forceinline__ uint32_t smem_u32(const void* p) {
    uint32_t a;
    asm("{ .reg .u64 t; cvta.to.shared.u64 t, %1; cvt.u32.u64 %0, t; }"
        : "=r"(a) : "l"(p));
    return a;
}
__device__ __forceinline__ void cp_async16(uint32_t dst, const void* src) {
    asm volatile("cp.async.cg.shared.global [%0], [%1], 16;"
                 :: "r"(dst), "l"(src));
}
#define CP_COMMIT() asm volatile("cp.async.commit_group;" ::: "memory")
#define CP_WAIT1()  asm volatile("cp.async.wait_group 1;" ::: "memory")

// ===========================================================================
// Split-tf32 GEMM, 3-stage cp.async ring, ONE __syncthreads per chunk,
// prefetch issued MID-COMPUTE (after kk-group 1) to avoid post-barrier
// LSU bursts. Raw A/B in smem; hi/lo split in registers. 128x128, K=32.
// ===========================================================================
#define SROW 36                          // 144 B row stride (16B-aligned)
#define SMAT (128 * SROW)                // floats per matrix per stage
#define NST 3
#define SMEM_MM (NST * 2 * SMAT * 4)     // 108 KB

__global__ __launch_bounds__(256, 2) void mm_hmma(const float* __restrict__ A,
                                                  const float* __restrict__ Bm,
                                                  const float* __restrict__ bias,
                                                  float* __restrict__ C, int ldc) {
    extern __shared__ float smem[];
    const uint32_t sb = smem_u32(smem);

    const int tid = threadIdx.x;
    const int wid = tid >> 5, lane = tid & 31;
    const int gid = lane >> 2, tig = lane & 3;
    const int wm = wid & 1;
    const int wn = wid >> 1;
    const int m0 = blockIdx.y * 128;
    const int n0 = blockIdx.x * 128;

    // staging coords: 2 threads/row; each covers 4 x 16B slots per matrix
    const int srow = tid >> 1;                 // 0..127
    const int scol = (tid & 1) * 4;            // slot base 0 or 4

    float acc[4][4][4] = {};

    // Prologue: stage chunks 0 and 1 into stages 0 and 1
    #pragma unroll
    for (int st = 0; st < 2; st++) {
        const int k0 = st * 32;
        const uint32_t bufA = sb + (2 * st) * SMAT * 4;
        const uint32_t bufB = sb + (2 * st + 1) * SMAT * 4;
        #pragma unroll
        for (int p = 0; p < 4; p++) {
            const int c4 = scol + p;           // float4 slot 0..7
            cp_async16(bufA + (srow * SROW + c4 * 4) * 4,
                       A + (size_t)(m0 + srow) * KTOT + k0 + c4 * 4);
            cp_async16(bufB + (srow * SROW + c4 * 4) * 4,
                       Bm + (size_t)(n0 + srow) * KTOT + k0 + c4 * 4);
        }
        CP_COMMIT();
    }

    const int NCH = KTOT / 32;                 // 24
    for (int ch = 0; ch < NCH; ch++) {
        CP_WAIT1();          // chunk ch resident (ch+1 may be in flight)
        __syncthreads();     // all warps retired chunk ch-1; data visible

        const int st = ch % NST;
        const float* sA = smem + (2 * st) * SMAT;
        const float* sB = smem + (2 * st + 1) * SMAT;

        #pragma unroll
        for (int kkg = 0; kkg < 4; kkg++) {
            const int kk = kkg * 8;
            uint32_t bh[4][2], bl[4][2];
            #pragma unroll
            for (int u = 0; u < 4; u++) {
                const int rb = (wn * 32 + u * 8 + gid) * SROW + kk + tig;
                float b0 = sB[rb], b1 = sB[rb + 4];
                bh[u][0] = hi_bits(b0);
                bh[u][1] = hi_bits(b1);
                bl[u][0] = fau(b0 - __uint_as_float(bh[u][0]));
                bl[u][1] = fau(b1 - __uint_as_float(bh[u][1]));
            }
            #pragma unroll
            for (int t = 0; t < 4; t++) {
                const int rb = (wm * 64 + t * 16 + gid) * SROW + kk + tig;
                float a0 = sA[rb];
                float a1 = sA[rb + 8 * SROW];
                float a2 = sA[rb + 4];
                float a3 = sA[rb + 8 * SROW + 4];
                uint32_t ah[4] = {hi_bits(a0), hi_bits(a1),
                                  hi_bits(a2), hi_bits(a3)};
                uint32_t al[4] = {fau(a0 - __uint_as_float(ah[0])),
                                  fau(a1 - __uint_as_float(ah[1])),
                                  fau(a2 - __uint_as_float(ah[2])),
                                  fau(a3 - __uint_as_float(ah[3]))};
                #pragma unroll
                for (int u = 0; u < 4; u++) {
                    mma_tf32(acc[t][u], ah, bh[u]);
                    mma_tf32(acc[t][u], ah, bl[u]);
                    mma_tf32(acc[t][u], al, bh[u]);
                }
            }
            // Mid-compute prefetch: chunk ch+2 into stage (ch+2)%3, whose
            // last reader (chunk ch-1) retired at this chunk's barrier.
            if (kkg == 1 && ch + 2 < NCH) {
                const int k0 = (ch + 2) * 32;
                const int pst = (ch + 2) % NST;
                const uint32_t bufA = sb + (2 * pst) * SMAT * 4;
                const uint32_t bufB = sb + (2 * pst + 1) * SMAT * 4;
                #pragma unroll
                for (int p = 0; p < 4; p++) {
                    const int c4 = scol + p;
                    cp_async16(bufA + (srow * SROW + c4 * 4) * 4,
                               A + (size_t)(m0 + srow) * KTOT + k0 + c4 * 4);
                    cp_async16(bufB + (srow * SROW + c4 * 4) * 4,
                               Bm + (size_t)(n0 + srow) * KTOT + k0 + c4 * 4);
                }
            }
        }
        CP_COMMIT();   // one group per chunk (empty at tail) keeps counts exact
    }

    const int rbase = m0 + wm * 64;
    const int cbase = n0 + wn * 32;
    #pragma unroll
    for (int t = 0; t < 4; t++) {
        #pragma unroll
        for (int u = 0; u < 4; u++) {
            const int c = cbase + u * 8 + tig * 2;
            float b0 = 0.f, b1 = 0.f;
            if (bias) { b0 = bias[c]; b1 = bias[c + 1]; }
            const int r0 = rbase + t * 16 + gid;
            *(float2*)(C + (size_t)r0 * ldc + c) =
                make_float2(acc[t][u][0] + b0, acc[t][u][1] + b1);
            *(float2*)(C + (size_t)(r0 + 8) * ldc + c) =
                make_float2(acc[t][u][2] + b0, acc[t][u][3] + b1);
        }
    }
}

// ===========================================================================
// Pre-pass: V -> V^T [bh][dim][key].
// ===========================================================================
__global__ __launch_bounds__(256) void prep_v() {
    __shared__ float sv[64][68];
    const int bh = blockIdx.y;
    const int kt = blockIdx.x;
    const int b = bh / HH, h = bh - b * HH;
    const int tid = threadIdx.x;
    #pragma unroll
    for (int p = 0; p < 4; p++) {
        const int j = tid + p * 256;
        const int key = j >> 4, c4 = (j & 15) * 4;
        float4 v = *(const float4*)(g_qkv +
            ((size_t)(b * NN + kt * 64 + key)) * E3 + h * 192 + 128 + c4);
        *(float4*)&sv[key][c4] = v;
    }
    __syncthreads();
    #pragma unroll
    for (int p = 0; p < 4; p++) {
        const int j = tid + p * 256;
        const int d = j >> 4, key4 = (j & 15) * 4;
        float4 o = make_float4(sv[key4 + 0][d], sv[key4 + 1][d],
                               sv[key4 + 2][d], sv[key4 + 3][d]);
        *(float4*)(g_vt + ((size_t)bh * 64 + d) * NN + kt * 64 + key4) = o;
    }
}

// ===========================================================================
// Flash attention, split-tf32 HMMA (unchanged — proven).
// ===========================================================================
#define ASTR 68
#define ATILE (64 * ASTR)
#define ATTN_SMEM (3 * ATILE * 4)   // 52224 B

__global__ __launch_bounds__(128, 4) void attn_hmma() {
    extern __shared__ float sm[];
    float* sQ = sm;
    float* sK = sQ + ATILE;
    float* sV = sK + ATILE;

    const int bh = blockIdx.y;
    const int q0 = blockIdx.x * 64;
    const int tid = threadIdx.x;
    const int wid = tid >> 5, lane = tid & 31;
    const int gid = lane >> 2, tig = lane & 3;
    const int b = bh / HH, h = bh - b * HH;
    const int r0 = wid * 16 + gid;
    const int qb = lane & ~3;
    const int src0 = qb + (tig >> 1);
    const int src1 = src0 + 2;
    const int esel = tig & 1;

    {
        const float* qg = g_qkv + ((size_t)(b * NN + q0)) * E3 + h * 192;
        #pragma unroll
        for (int p = 0; p < 8; p++) {
            const int j = tid + p * 128;
            const int r = j >> 4, c4 = (j & 15) * 4;
            float4 v = *(const float4*)(qg + (size_t)r * E3 + c4);
            *(float4*)&sQ[r * ASTR + c4] =
                make_float4(v.x * 8.f, v.y * 8.f, v.z * 8.f, v.w * 8.f);
        }
    }

    float oa[8][4] = {};
    float mrow0 = -1e30f, mrow1 = -1e30f, lrow0 = 0.f, lrow1 = 0.f;

    for (int kt = 0; kt < 16; kt++) {
        __syncthreads();
        {
            const float* kg = g_qkv + ((size_t)(b * NN + kt * 64)) * E3 + h * 192 + 64;
            const float* vg = g_vt + ((size_t)bh * 64) * NN + kt * 64;
            #pragma unroll
            for (int p = 0; p < 8; p++) {
                const int j = tid + p * 128;
                const int r = j >> 4, c4 = (j & 15) * 4;
                *(float4*)&sK[r * ASTR + c4] = *(const float4*)(kg + (size_t)r * E3 + c4);
                *(float4*)&sV[r * ASTR + c4] = *(const float4*)(vg + (size_t)r * NN + c4);
            }
        }
        __syncthreads();

        float s[8][4] = {};
        #pragma unroll
        for (int kk = 0; kk < 64; kk += 8) {
            float a0 = sQ[r0 * ASTR + kk + tig];
            float a1 = sQ[(r0 + 8) * ASTR + kk + tig];
            float a2 = sQ[r0 * ASTR + kk + tig + 4];
            float a3 = sQ[(r0 + 8) * ASTR + kk + tig + 4];
            uint32_t ah[4] = {hi_bits(a0), hi_bits(a1), hi_bits(a2), hi_bits(a3)};
            uint32_t al[4] = {fau(a0 - __uint_as_float(ah[0])),
                              fau(a1 - __uint_as_float(ah[1])),
                              fau(a2 - __uint_as_float(ah[2])),
                              fau(a3 - __uint_as_float(ah[3]))};
            #pragma unroll
            for (int u = 0; u < 8; u++) {
                const int n = u * 8 + gid;
                float b0 = sK[n * ASTR + kk + tig];
                float b1 = sK[n * ASTR + kk + tig + 4];
                uint32_t bh[2] = {hi_bits(b0), hi_bits(b1)};
                uint32_t bl[2] = {fau(b0 - __uint_as_float(bh[0])),
                                  fau(b1 - __uint_as_float(bh[1]))};
                mma_tf32(s[u], ah, bh);
                mma_tf32(s[u], ah, bl);
                mma_tf32(s[u], al, bh);
            }
        }

        float mt0 = -1e30f, mt1 = -1e30f;
        #pragma unroll
        for (int u = 0; u < 8; u++) {
            mt0 = fmaxf(mt0, fmaxf(s[u][0], s[u][1]));
            mt1 = fmaxf(mt1, fmaxf(s[u][2], s[u][3]));
        }
        #pragma unroll
        for (int off = 1; off < 4; off <<= 1) {
            mt0 = fmaxf(mt0, __shfl_xor_sync(0xffffffffu, mt0, off));
            mt1 = fmaxf(mt1, __shfl_xor_sync(0xffffffffu, mt1, off));
        }
        const float mn0 = fmaxf(mrow0, mt0);
        const float mn1 = fmaxf(mrow1, mt1);
        const float f0 = __expf(mrow0 - mn0);
        const float f1 = __expf(mrow1 - mn1);
        float ls0 = 0.f, ls1 = 0.f;
        #pragma unroll
        for (int u = 0; u < 8; u++) {
            s[u][0] = __expf(s[u][0] - mn0);
            s[u][1] = __expf(s[u][1] - mn0);
            s[u][2] = __expf(s[u][2] - mn1);
            s[u][3] = __expf(s[u][3] - mn1);
            ls0 += s[u][0] + s[u][1];
            ls1 += s[u][2] + s[u][3];
        }
        #pragma unroll
        for (int off = 1; off < 4; off <<= 1) {
            ls0 += __shfl_xor_sync(0xffffffffu, ls0, off);
            ls1 += __shfl_xor_sync(0xffffffffu, ls1, off);
        }
        lrow0 = lrow0 * f0 + ls0;  mrow0 = mn0;
        lrow1 = lrow1 * f1 + ls1;  mrow1 = mn1;

        #pragma unroll
        for (int u = 0; u < 8; u++) {
            oa[u][0] *= f0; oa[u][1] *= f0;
            oa[u][2] *= f1; oa[u][3] *= f1;
        }

        #pragma unroll
        for (int kk = 0; kk < 8; kk++) {
            float v00 = __shfl_sync(0xffffffffu, s[kk][0], src0);
            float v01 = __shfl_sync(0xffffffffu, s[kk][1], src0);
            float v10 = __shfl_sync(0xffffffffu, s[kk][2], src0);
            float v11 = __shfl_sync(0xffffffffu, s[kk][3], src0);
            float w00 = __shfl_sync(0xffffffffu, s[kk][0], src1);
            float w01 = __shfl_sync(0xffffffffu, s[kk][1], src1);
            float w10 = __shfl_sync(0xffffffffu, s[kk][2], src1);
            float w11 = __shfl_sync(0xffffffffu, s[kk][3], src1);
            float a0 = esel ? v01 : v00;
            float a1 = esel ? v11 : v10;
            float a2 = esel ? w01 : w00;
            float a3 = esel ? w11 : w10;
            uint32_t ah[4] = {hi_bits(a0), hi_bits(a1), hi_bits(a2), hi_bits(a3)};
            uint32_t al[4] = {fau(a0 - __uint_as_float(ah[0])),
                              fau(a1 - __uint_as_float(ah[1])),
                              fau(a2 - __uint_as_float(ah[2])),
                              fau(a3 - __uint_as_float(ah[3]))};
            #pragma unroll
            for (int u = 0; u < 8; u++) {
                const int n = u * 8 + gid;
                float b0 = sV[n * ASTR + kk * 8 + tig];
                float b1 = sV[n * ASTR + kk * 8 + tig + 4];
                uint32_t bh[2] = {hi_bits(b0), hi_bits(b1)};
                uint32_t bl[2] = {fau(b0 - __uint_as_float(bh[0])),
                                  fau(b1 - __uint_as_float(bh[1]))};
                mma_tf32(oa[u], ah, bh);
                mma_tf32(oa[u], ah, bl);
                mma_tf32(oa[u], al, bh);
            }
        }
    }

    const float il0 = 1.f / lrow0;
    const float il1 = 1.f / lrow1;
    #pragma unroll
    for (int u = 0; u < 8; u++) {
        const int col = h * 64 + u * 8 + 2 * tig;
        *(float2*)&g_o[((size_t)(b * NN + q0 + r0)) * DH + col] =
            make_float2(oa[u][0] * il0, oa[u][1] * il0);
        *(float2*)&g_o[((size_t)(b * NN + q0 + r0 + 8)) * DH + col] =
            make_float2(oa[u][2] * il1, oa[u][3] * il1);
    }
}

// ===========================================================================
extern "C" void kernel_launch(void* const* d_in, const int* in_sizes, int n_in,
                              void* d_out, int out_size) {
    const float* img  = (const float*)d_in[0];   // [8,1024,768]
    const float* Wqkv = (const float*)d_in[1];   // [2304,768]
    const float* Wfc  = (const float*)d_in[2];   // [768,768]
    const float* bfc  = (const float*)d_in[3];   // [768]
    float* out = (float*)d_out;                  // [8,1024,768]

    void* qkvp = nullptr;
    void* op = nullptr;
    cudaGetSymbolAddress(&qkvp, g_qkv);
    cudaGetSymbolAddress(&op, g_o);

    cudaFuncSetAttribute(mm_hmma, cudaFuncAttributeMaxDynamicSharedMemorySize,
                         SMEM_MM);
    cudaFuncSetAttribute(attn_hmma, cudaFuncAttributeMaxDynamicSharedMemorySize,
                         ATTN_SMEM);

    // 1) QKV projection
    mm_hmma<<<dim3(E3 / 128, NTOK / 128), 256, SMEM_MM>>>(img, Wqkv, nullptr,
                                                          (float*)qkvp, E3);
    // 2) V transpose
    prep_v<<<dim3(16, NBH), 256>>>();
    // 3) Flash attention
    attn_hmma<<<dim3(NN / 64, NBH), 128, ATTN_SMEM>>>();
    // 4) Output projection + bias
    mm_hmma<<<dim3(DIM / 128, NTOK / 128), 256, SMEM_MM>>>((const float*)op, Wfc,
                                                           bfc, out, DIM);
}

// round 16
// speedup vs baseline: 1.6247x; 1.5340x over previous
#include <cuda_runtime.h>
#include <cuda_fp16.h>
#include <cstdint>

#define BB 8
#define NN 1024
#define HH 12
#define DIM 768
#define DH  768
#define E3  2304
#define NTOK (BB*NN)
#define KTOT 768
#define NBH (BB*HH)   // 96

// ===== scratch (device globals; no runtime allocation) =====
__device__ float g_qkv[(size_t)NTOK * E3];
__device__ __align__(16) __half g_imh[(size_t)NTOK * DIM];
__device__ __align__(16) __half g_iml[(size_t)NTOK * DIM];
__device__ __align__(16) __half g_wqh[(size_t)E3 * DIM];
__device__ __align__(16) __half g_wql[(size_t)E3 * DIM];
__device__ __align__(16) __half g_wfh[(size_t)DIM * DH];
__device__ __align__(16) __half g_wfl[(size_t)DIM * DH];
__device__ __align__(16) __half g_oh[(size_t)NTOK * DH];
__device__ __align__(16) __half g_ol[(size_t)NTOK * DH];
__device__ __align__(16) __half g_qh[(size_t)NBH * NN * 64];
__device__ __align__(16) __half g_ql[(size_t)NBH * NN * 64];
__device__ __align__(16) __half g_kh[(size_t)NBH * NN * 64];
__device__ __align__(16) __half g_kl[(size_t)NBH * NN * 64];
__device__ __align__(16) __half g_vh[(size_t)NBH * 64 * NN];   // [bh][dim][key]
__device__ __align__(16) __half g_vl[(size_t)NBH * 64 * NN];

// ===== helpers =====
// Split two floats into packed half2 hi (rn) and half2 lo (residual, rn).
__device__ __forceinline__ void split2(float x0, float x1,
                                       uint32_t& h, uint32_t& l) {
    __half2 hh = __floats2half2_rn(x0, x1);          // low = x0, high = x1
    float2 hf = __half22float2(hh);
    __half2 ll = __floats2half2_rn(x0 - hf.x, x1 - hf.y);
    h = *reinterpret_cast<uint32_t*>(&hh);
    l = *reinterpret_cast<uint32_t*>(&ll);
}

__device__ __forceinline__ void mma_f16(float* d, const uint32_t* a,
                                        const uint32_t* b) {
    asm volatile(
        "mma.sync.aligned.m16n8k16.row.col.f32.f16.f16.f32 "
        "{%0,%1,%2,%3}, {%4,%5,%6,%7}, {%8,%9}, {%0,%1,%2,%3};"
        : "+f"(d[0]), "+f"(d[1]), "+f"(d[2]), "+f"(d[3])
        : "r"(a[0]), "r"(a[1]), "r"(a[2]), "r"(a[3]), "r"(b[0]), "r"(b[1]));
}

__device__ __forceinline__ uint32_t smem_u32(const void* p) {
    uint32_t a;
    asm("{ .reg .u64 t; cvta.to.shared.u64 t, %1; cvt.u32.u64 %0, t; }"
        : "=r"(a) : "l"(p));
    return a;
}
__device__ __forceinline__ void cp_async16(uint32_t dst, const void* src) {
    asm volatile("cp.async.cg.shared.global [%0], [%1], 16;"
                 :: "r"(dst), "l"(src));
}
#define CP_COMMIT() asm volatile("cp.async.commit_group;" ::: "memory")
#define CP_WAIT1()  asm volatile("cp.async.wait_group 1;" ::: "memory")

// ===========================================================================
// prep: generic fp32 -> half hi/lo plane split (grid covers n/4 float4s)
// ===========================================================================
__global__ __launch_bounds__(256) void prep_split(const float* __restrict__ src,
                                                  __half* __restrict__ dh,
                                                  __half* __restrict__ dl,
                                                  int n4) {
    const int i = blockIdx.x * 256 + threadIdx.x;
    if (i >= n4) return;
    float4 v = ((const float4*)src)[i];
    uint32_t h0, l0, h1, l1;
    split2(v.x, v.y, h0, l0);
    split2(v.z, v.w, h1, l1);
    ((uint2*)dh)[i] = make_uint2(h0, h1);
    ((uint2*)dl)[i] = make_uint2(l0, l1);
}

// ===========================================================================
// prep: Q (x8) and K from g_qkv -> half hi/lo planes [bh][tok][64]
// ===========================================================================
__global__ __launch_bounds__(256) void prep_qk() {
    const int j = blockIdx.x * 256 + threadIdx.x;   // NBH*NN*16
    const int c4 = (j & 15) * 4;
    const int bt = j >> 4;
    const int bh = bt >> 10, tok = bt & 1023;
    const int b = bh / HH, h = bh - b * HH;
    const float* base = g_qkv + ((size_t)(b * NN + tok)) * E3 + h * 192;
    float4 q = *(const float4*)(base + c4);
    float4 k = *(const float4*)(base + 64 + c4);
    uint32_t qh0, ql0, qh1, ql1, kh0, kl0, kh1, kl1;
    split2(q.x * 8.f, q.y * 8.f, qh0, ql0);
    split2(q.z * 8.f, q.w * 8.f, qh1, ql1);
    split2(k.x, k.y, kh0, kl0);
    split2(k.z, k.w, kh1, kl1);
    const size_t o = (((size_t)bt) * 64 + c4) >> 2;   // uint2 index
    ((uint2*)g_qh)[o] = make_uint2(qh0, qh1);
    ((uint2*)g_ql)[o] = make_uint2(ql0, ql1);
    ((uint2*)g_kh)[o] = make_uint2(kh0, kh1);
    ((uint2*)g_kl)[o] = make_uint2(kl0, kl1);
}

// ===========================================================================
// prep: V -> V^T [bh][dim][key], split hi/lo
// ===========================================================================
__global__ __launch_bounds__(256) void prep_v() {
    __shared__ float sv[64][68];
    const int bh = blockIdx.y, kt = blockIdx.x;
    const int b = bh / HH, h = bh - b * HH;
    const int tid = threadIdx.x;
    #pragma unroll
    for (int p = 0; p < 4; p++) {
        const int j = tid + p * 256;
        const int key = j >> 4, c4 = (j & 15) * 4;
        float4 v = *(const float4*)(g_qkv +
            ((size_t)(b * NN + kt * 64 + key)) * E3 + h * 192 + 128 + c4);
        *(float4*)&sv[key][c4] = v;
    }
    __syncthreads();
    #pragma unroll
    for (int p = 0; p < 4; p++) {
        const int j = tid + p * 256;
        const int d = j >> 4, key4 = (j & 15) * 4;
        uint32_t h0, l0, h1, l1;
        split2(sv[key4 + 0][d], sv[key4 + 1][d], h0, l0);
        split2(sv[key4 + 2][d], sv[key4 + 3][d], h1, l1);
        const size_t o = ((((size_t)bh * 64 + d)) * NN + kt * 64 + key4) >> 2;
        ((uint2*)g_vh)[o] = make_uint2(h0, h1);
        ((uint2*)g_vl)[o] = make_uint2(l0, l1);
    }
}

// ===========================================================================
// Split-fp16 GEMM (3-pass, m16n8k16): C = A@B^T (+bias). Half hi/lo planes
// staged via cp.async double buffer. 128x128 tile, 8 warps, K-chunk 32.
// ===========================================================================
#define MSTRW 20                        // words per row (80 B) — conflict-free
#define MPLW (128 * MSTRW)              // 2560 words per plane
#define MSTAGEW (4 * MPLW)              // Ah, Al, Bh, Bl
#define SMEM_MM (2 * MSTAGEW * 4)       // 81920 B

__global__ __launch_bounds__(256, 2) void mm_f16(
        const __half* __restrict__ Ah, const __half* __restrict__ Al,
        const __half* __restrict__ Bh, const __half* __restrict__ Bl,
        const float* __restrict__ bias, float* __restrict__ C, int ldc) {
    extern __shared__ uint32_t smw[];
    const uint32_t sb = smem_u32(smw);

    const int tid = threadIdx.x;
    const int wid = tid >> 5, lane = tid & 31;
    const int gid = lane >> 2, tig = lane & 3;
    const int wm = wid & 1, wn = wid >> 1;
    const int m0 = blockIdx.y * 128, n0 = blockIdx.x * 128;
    const int srow = tid >> 1;              // 0..127
    const int sc = (tid & 1) * 2;           // 16B-chunk base: {0,1} or {2,3}

    float acc[4][4][4] = {};

#define MM_STAGE(CH, ST) do {                                                  \
        const int _k0 = (CH) * 32;                                             \
        const uint32_t _d = sb + (ST) * MSTAGEW * 4 + srow * 80;               \
        _Pragma("unroll")                                                      \
        for (int _c = 0; _c < 2; _c++) {                                       \
            const int c16 = sc + _c;                                           \
            cp_async16(_d + 0 * MPLW * 4 + c16 * 16,                           \
                       Ah + (size_t)(m0 + srow) * KTOT + _k0 + c16 * 8);       \
            cp_async16(_d + 1 * MPLW * 4 + c16 * 16,                           \
                       Al + (size_t)(m0 + srow) * KTOT + _k0 + c16 * 8);       \
            cp_async16(_d + 2 * MPLW * 4 + c16 * 16,                           \
                       Bh + (size_t)(n0 + srow) * KTOT + _k0 + c16 * 8);       \
            cp_async16(_d + 3 * MPLW * 4 + c16 * 16,                           \
                       Bl + (size_t)(n0 + srow) * KTOT + _k0 + c16 * 8);       \
        }                                                                      \
    } while (0)

    MM_STAGE(0, 0); CP_COMMIT();
    MM_STAGE(1, 1); CP_COMMIT();

    const int NCH = KTOT / 32;              // 24
    for (int ch = 0; ch < NCH; ch++) {
        CP_WAIT1();
        __syncthreads();
        const int st = ch & 1;
        const uint32_t* pAh = smw + st * MSTAGEW;
        const uint32_t* pAl = pAh + MPLW;
        const uint32_t* pBh = pAh + 2 * MPLW;
        const uint32_t* pBl = pAh + 3 * MPLW;

        #pragma unroll
        for (int kkg = 0; kkg < 2; kkg++) {
            const int pb = tig + 8 * kkg;
            uint32_t bhf[4][2], blf[4][2];
            #pragma unroll
            for (int u = 0; u < 4; u++) {
                const int n = wn * 32 + u * 8 + gid;
                bhf[u][0] = pBh[n * MSTRW + pb];
                bhf[u][1] = pBh[n * MSTRW + pb + 4];
                blf[u][0] = pBl[n * MSTRW + pb];
                blf[u][1] = pBl[n * MSTRW + pb + 4];
            }
            #pragma unroll
            for (int t = 0; t < 4; t++) {
                const int r = wm * 64 + t * 16 + gid;
                uint32_t ahf[4] = {pAh[r * MSTRW + pb], pAh[(r + 8) * MSTRW + pb],
                                   pAh[r * MSTRW + pb + 4], pAh[(r + 8) * MSTRW + pb + 4]};
                uint32_t alf[4] = {pAl[r * MSTRW + pb], pAl[(r + 8) * MSTRW + pb],
                                   pAl[r * MSTRW + pb + 4], pAl[(r + 8) * MSTRW + pb + 4]};
                #pragma unroll
                for (int u = 0; u < 4; u++) {
                    mma_f16(acc[t][u], ahf, bhf[u]);
                    mma_f16(acc[t][u], ahf, blf[u]);
                    mma_f16(acc[t][u], alf, bhf[u]);
                }
            }
        }
        __syncthreads();
        if (ch + 2 < NCH) MM_STAGE(ch + 2, st);
        CP_COMMIT();
    }
#undef MM_STAGE

    const int rbase = m0 + wm * 64;
    const int cbase = n0 + wn * 32;
    #pragma unroll
    for (int t = 0; t < 4; t++) {
        #pragma unroll
        for (int u = 0; u < 4; u++) {
            const int c = cbase + u * 8 + tig * 2;
            float b0 = 0.f, b1 = 0.f;
            if (bias) { b0 = bias[c]; b1 = bias[c + 1]; }
            const int r0 = rbase + t * 16 + gid;
            *(float2*)(C + (size_t)r0 * ldc + c) =
                make_float2(acc[t][u][0] + b0, acc[t][u][1] + b1);
            *(float2*)(C + (size_t)(r0 + 8) * ldc + c) =
                make_float2(acc[t][u][2] + b0, acc[t][u][3] + b1);
        }
    }
}

// ===========================================================================
// Flash attention, split-fp16 (m16n8k16). 128 thr, q-tile 64, 4 CTA/SM.
// QK acc layout == PV A-frag layout -> no shuffles; P split in registers.
// ===========================================================================
#define ASTRW 36                        // words per row (144 B) — conflict-free
#define APLW (64 * ASTRW)               // 2304 words per plane
#define ATTN_SMEM (6 * APLW * 4)        // 55296 B

__global__ __launch_bounds__(128, 4) void attn_f16() {
    extern __shared__ uint32_t smw[];
    uint32_t* sQh = smw;
    uint32_t* sQl = smw + APLW;
    uint32_t* sKh = smw + 2 * APLW;
    uint32_t* sKl = smw + 3 * APLW;
    uint32_t* sVh = smw + 4 * APLW;
    uint32_t* sVl = smw + 5 * APLW;

    const int bh = blockIdx.y, q0 = blockIdx.x * 64;
    const int tid = threadIdx.x;
    const int wid = tid >> 5, lane = tid & 31;
    const int gid = lane >> 2, tig = lane & 3;
    const int b = bh / HH, h = bh - b * HH;
    const int r0 = wid * 16 + gid;

    // Stage Q planes (64 x 64 halves each)
    {
        const __half* qh = g_qh + ((size_t)bh * NN + q0) * 64;
        const __half* ql = g_ql + ((size_t)bh * NN + q0) * 64;
        #pragma unroll
        for (int p = 0; p < 4; p++) {
            const int j = tid + p * 128;          // 0..511
            const int r = j >> 3, c16 = j & 7;
            *(uint4*)((char*)sQh + r * 144 + c16 * 16) =
                *(const uint4*)(qh + (size_t)r * 64 + c16 * 8);
            *(uint4*)((char*)sQl + r * 144 + c16 * 16) =
                *(const uint4*)(ql + (size_t)r * 64 + c16 * 8);
        }
    }

    float oa[8][4] = {};
    float mrow0 = -1e30f, mrow1 = -1e30f, lrow0 = 0.f, lrow1 = 0.f;

    for (int kt = 0; kt < 16; kt++) {
        __syncthreads();
        {
            const __half* kh = g_kh + ((size_t)bh * NN + kt * 64) * 64;
            const __half* kl = g_kl + ((size_t)bh * NN + kt * 64) * 64;
            const __half* vh = g_vh + ((size_t)bh * 64) * NN + kt * 64;
            const __half* vl = g_vl + ((size_t)bh * 64) * NN + kt * 64;
            #pragma unroll
            for (int p = 0; p < 4; p++) {
                const int j = tid + p * 128;
                const int r = j >> 3, c16 = j & 7;
                *(uint4*)((char*)sKh + r * 144 + c16 * 16) =
                    *(const uint4*)(kh + (size_t)r * 64 + c16 * 8);
                *(uint4*)((char*)sKl + r * 144 + c16 * 16) =
                    *(const uint4*)(kl + (size_t)r * 64 + c16 * 8);
                *(uint4*)((char*)sVh + r * 144 + c16 * 16) =
                    *(const uint4*)(vh + (size_t)r * NN + c16 * 8);
                *(uint4*)((char*)sVl + r * 144 + c16 * 16) =
                    *(const uint4*)(vl + (size_t)r * NN + c16 * 8);
            }
        }
        __syncthreads();

        // ---- S = Q K^T (3-pass split-fp16) ----
        float s[8][4] = {};
        #pragma unroll
        for (int kkg = 0; kkg < 4; kkg++) {
            const int pb = tig + 8 * kkg;
            uint32_t ahf[4] = {sQh[r0 * ASTRW + pb], sQh[(r0 + 8) * ASTRW + pb],
                               sQh[r0 * ASTRW + pb + 4], sQh[(r0 + 8) * ASTRW + pb + 4]};
            uint32_t alf[4] = {sQl[r0 * ASTRW + pb], sQl[(r0 + 8) * ASTRW + pb],
                               sQl[r0 * ASTRW + pb + 4], sQl[(r0 + 8) * ASTRW + pb + 4]};
            #pragma unroll
            for (int u = 0; u < 8; u++) {
                const int n = u * 8 + gid;
                uint32_t bhf[2] = {sKh[n * ASTRW + pb], sKh[n * ASTRW + pb + 4]};
                uint32_t blf[2] = {sKl[n * ASTRW + pb], sKl[n * ASTRW + pb + 4]};
                mma_f16(s[u], ahf, bhf);
                mma_f16(s[u], ahf, blf);
                mma_f16(s[u], alf, bhf);
            }
        }

        // ---- warp-local online softmax (rows r0, r0+8) ----
        float mt0 = -1e30f, mt1 = -1e30f;
        #pragma unroll
        for (int u = 0; u < 8; u++) {
            mt0 = fmaxf(mt0, fmaxf(s[u][0], s[u][1]));
            mt1 = fmaxf(mt1, fmaxf(s[u][2], s[u][3]));
        }
        #pragma unroll
        for (int off = 1; off < 4; off <<= 1) {
            mt0 = fmaxf(mt0, __shfl_xor_sync(0xffffffffu, mt0, off));
            mt1 = fmaxf(mt1, __shfl_xor_sync(0xffffffffu, mt1, off));
        }
        const float mn0 = fmaxf(mrow0, mt0);
        const float mn1 = fmaxf(mrow1, mt1);
        const float f0 = __expf(mrow0 - mn0);
        const float f1 = __expf(mrow1 - mn1);
        float ls0 = 0.f, ls1 = 0.f;
        #pragma unroll
        for (int u = 0; u < 8; u++) {
            s[u][0] = __expf(s[u][0] - mn0);
            s[u][1] = __expf(s[u][1] - mn0);
            s[u][2] = __expf(s[u][2] - mn1);
            s[u][3] = __expf(s[u][3] - mn1);
            ls0 += s[u][0] + s[u][1];
            ls1 += s[u][2] + s[u][3];
        }
        #pragma unroll
        for (int off = 1; off < 4; off <<= 1) {
            ls0 += __shfl_xor_sync(0xffffffffu, ls0, off);
            ls1 += __shfl_xor_sync(0xffffffffu, ls1, off);
        }
        lrow0 = lrow0 * f0 + ls0;  mrow0 = mn0;
        lrow1 = lrow1 * f1 + ls1;  mrow1 = mn1;

        #pragma unroll
        for (int u = 0; u < 8; u++) {
            oa[u][0] *= f0; oa[u][1] *= f0;
            oa[u][2] *= f1; oa[u][3] *= f1;
        }

        // ---- O += P V : acc layout IS the A-frag layout (no shuffles) ----
        #pragma unroll
        for (int g = 0; g < 4; g++) {
            uint32_t ahf[4], alf[4];
            split2(s[2 * g][0], s[2 * g][1], ahf[0], alf[0]);
            split2(s[2 * g][2], s[2 * g][3], ahf[1], alf[1]);
            split2(s[2 * g + 1][0], s[2 * g + 1][1], ahf[2], alf[2]);
            split2(s[2 * g + 1][2], s[2 * g + 1][3], ahf[3], alf[3]);
            const int pb = tig + 8 * g;
            #pragma unroll
            for (int u = 0; u < 8; u++) {
                const int n = u * 8 + gid;
                uint32_t bhf[2] = {sVh[n * ASTRW + pb], sVh[n * ASTRW + pb + 4]};
                uint32_t blf[2] = {sVl[n * ASTRW + pb], sVl[n * ASTRW + pb + 4]};
                mma_f16(oa[u], ahf, bhf);
                mma_f16(oa[u], ahf, blf);
                mma_f16(oa[u], alf, bhf);
            }
        }
    }

    // Epilogue: O /= l, split to half planes for the out-projection
    const float il0 = 1.f / lrow0;
    const float il1 = 1.f / lrow1;
    #pragma unroll
    for (int u = 0; u < 8; u++) {
        const int col = h * 64 + u * 8 + 2 * tig;
        uint32_t hh, ll;
        split2(oa[u][0] * il0, oa[u][1] * il0, hh, ll);
        size_t idx = (((size_t)(b * NN + q0 + r0)) * DH + col) >> 1;
        ((uint32_t*)g_oh)[idx] = hh;
        ((uint32_t*)g_ol)[idx] = ll;
        split2(oa[u][2] * il1, oa[u][3] * il1, hh, ll);
        idx = (((size_t)(b * NN + q0 + r0 + 8)) * DH + col) >> 1;
        ((uint32_t*)g_oh)[idx] = hh;
        ((uint32_t*)g_ol)[idx] = ll;
    }
}

// ===========================================================================
extern "C" void kernel_launch(void* const* d_in, const int* in_sizes, int n_in,
                              void* d_out, int out_size) {
    const float* img  = (const float*)d_in[0];   // [8,1024,768]
    const float* Wqkv = (const float*)d_in[1];   // [2304,768]
    const float* Wfc  = (const float*)d_in[2];   // [768,768]
    const float* bfc  = (const float*)d_in[3];   // [768]
    float* out = (float*)d_out;                  // [8,1024,768]

    void *qkvp, *imh, *iml, *wqh, *wql, *wfh, *wfl, *oh, *ol;
    cudaGetSymbolAddress(&qkvp, g_qkv);
    cudaGetSymbolAddress(&imh, g_imh);  cudaGetSymbolAddress(&iml, g_iml);
    cudaGetSymbolAddress(&wqh, g_wqh);  cudaGetSymbolAddress(&wql, g_wql);
    cudaGetSymbolAddress(&wfh, g_wfh);  cudaGetSymbolAddress(&wfl, g_wfl);
    cudaGetSymbolAddress(&oh, g_oh);    cudaGetSymbolAddress(&ol, g_ol);

    cudaFuncSetAttribute(mm_f16, cudaFuncAttributeMaxDynamicSharedMemorySize,
                         SMEM_MM);
    cudaFuncSetAttribute(attn_f16, cudaFuncAttributeMaxDynamicSharedMemorySize,
                         ATTN_SMEM);

    // 0) split inputs into half hi/lo planes
    prep_split<<<NTOK * DIM / 4 / 256, 256>>>(img, (__half*)imh, (__half*)iml,
                                              NTOK * DIM / 4);
    prep_split<<<E3 * DIM / 4 / 256, 256>>>(Wqkv, (__half*)wqh, (__half*)wql,
                                            E3 * DIM / 4);
    prep_split<<<DIM * DH / 4 / 256, 256>>>(Wfc, (__half*)wfh, (__half*)wfl,
                                            DIM * DH / 4);

    // 1) QKV projection (fp32 result)
    mm_f16<<<dim3(E3 / 128, NTOK / 128), 256, SMEM_MM>>>(
        (const __half*)imh, (const __half*)iml,
        (const __half*)wqh, (const __half*)wql, nullptr, (float*)qkvp, E3);

    // 2) split Q(x8)/K, transpose+split V
    prep_qk<<<NBH * NN * 16 / 256, 256>>>();
    prep_v<<<dim3(16, NBH), 256>>>();

    // 3) flash attention (emits half planes g_oh/g_ol)
    attn_f16<<<dim3(NN / 64, NBH), 128, ATTN_SMEM>>>();

    // 4) output projection + bias
    mm_f16<<<dim3(DIM / 128, NTOK / 128), 256, SMEM_MM>>>(
        (const __half*)oh, (const __half*)ol,
        (const __half*)wfh, (const __half*)wfl, bfc, out, DIM);
}